// round 5
// baseline (speedup 1.0000x reference)
#include <cuda_runtime.h>
#include <cuda_bf16.h>
#include <cstdint>

#define BSCD 16777216        // B*S*C*D per tensor

// ---------------- smem arena (offsets in bf16 halves) ----------------
// R1/R2: QKV of spec/spat: Q[64][264] | K[64][136] | Vt[128][72]
#define R1     0
#define R2     34816
#define QOFF   0
#define KOFF   16896
#define VOFF   25600
#define SLOTA  69632         // core_spec -> (P2 Wbuf0) -> att_spec   [64][264]
#define SLOTB  86528         // core_spat -> att_spat                 [64][264]
#define WX     103424        // P2 Wbuf1 (12288 halves)
#define ARENA_H 115712
#define SMEM_BYTES (ARENA_H * 2)   // 231424 B

// Scratch weights (__device__ globals; allocation-free rule)
__device__ __nv_bfloat16 g_wqkv[2][512 * 256];   // [n][k] bf16 (LN-gain folded)
__device__ float         g_bfold[2][512];
__device__ __nv_bfloat16 g_wo[2][256 * 256];     // [n][k] bf16

__device__ __forceinline__ uint32_t pack_bf16(float lo, float hi) {
    __nv_bfloat162 h = __floats2bfloat162_rn(lo, hi);
    return *reinterpret_cast<uint32_t*>(&h);
}
__device__ __forceinline__ void mma_bf16(float c[4], const uint32_t a[4], const uint32_t b[2]) {
    asm volatile(
        "mma.sync.aligned.m16n8k16.row.col.f32.bf16.bf16.f32 "
        "{%0,%1,%2,%3}, {%4,%5,%6,%7}, {%8,%9}, {%0,%1,%2,%3};"
        : "+f"(c[0]), "+f"(c[1]), "+f"(c[2]), "+f"(c[3])
        : "r"(a[0]), "r"(a[1]), "r"(a[2]), "r"(a[3]), "r"(b[0]), "r"(b[1]));
}
__device__ __forceinline__ void ldsm4(uint32_t& r0, uint32_t& r1, uint32_t& r2, uint32_t& r3,
                                      uint32_t addr) {
    asm volatile("ldmatrix.sync.aligned.m8n8.x4.shared.b16 {%0,%1,%2,%3}, [%4];"
                 : "=r"(r0), "=r"(r1), "=r"(r2), "=r"(r3) : "r"(addr));
}
__device__ __forceinline__ uint32_t smaddr(const void* p) {
    return (uint32_t)__cvta_generic_to_shared(p);
}
__device__ __forceinline__ void cp_async16(uint32_t dst, const void* src) {
    asm volatile("cp.async.cg.shared.global [%0], [%1], 16;" :: "r"(dst), "l"(src));
}
__device__ __forceinline__ void cp_commit() { asm volatile("cp.async.commit_group;"); }
__device__ __forceinline__ void cp_wait0()  { asm volatile("cp.async.wait_group 0;"); }
__device__ __forceinline__ void cp_wait1()  { asm volatile("cp.async.wait_group 1;"); }

// ---------------------------------------------------------------------------
// Kernel 1: prep (unchanged). grid (768, 2), block 256.
// ---------------------------------------------------------------------------
__global__ __launch_bounds__(256) void prep_kernel(
    const float* __restrict__ Wq_s2t, const float* __restrict__ bq_s2t,
    const float* __restrict__ Wk_s2t, const float* __restrict__ bk_s2t,
    const float* __restrict__ Wv_s2t, const float* __restrict__ bv_s2t,
    const float* __restrict__ Wq_t2s, const float* __restrict__ bq_t2s,
    const float* __restrict__ Wk_t2s, const float* __restrict__ bk_t2s,
    const float* __restrict__ Wv_t2s, const float* __restrict__ bv_t2s,
    const float* __restrict__ Wo_s2t, const float* __restrict__ Wo_t2s,
    const float* __restrict__ g_spec_q, const float* __restrict__ b_spec_q,
    const float* __restrict__ g_spec_kv, const float* __restrict__ b_spec_kv,
    const float* __restrict__ g_spat_q, const float* __restrict__ b_spat_q,
    const float* __restrict__ g_spat_kv, const float* __restrict__ b_spat_kv)
{
    int n = blockIdx.x, t = blockIdx.y, k = threadIdx.x;
    __shared__ float red[256];

    if (n < 512) {
        const float *W, *g, *bln, *bbase;
        int nc, stride;
        if (t == 0) {
            if (n < 256)      { W = Wq_s2t; nc = n;       stride = 256; g = g_spec_q;  bln = b_spec_q;  bbase = bq_s2t; }
            else if (n < 384) { W = Wk_t2s; nc = n - 256; stride = 128; g = g_spec_kv; bln = b_spec_kv; bbase = bk_t2s; }
            else              { W = Wv_t2s; nc = n - 384; stride = 128; g = g_spec_kv; bln = b_spec_kv; bbase = bv_t2s; }
        } else {
            if (n < 256)      { W = Wq_t2s; nc = n;       stride = 256; g = g_spat_q;  bln = b_spat_q;  bbase = bq_t2s; }
            else if (n < 384) { W = Wk_s2t; nc = n - 256; stride = 128; g = g_spat_kv; bln = b_spat_kv; bbase = bk_s2t; }
            else              { W = Wv_s2t; nc = n - 384; stride = 128; g = g_spat_kv; bln = b_spat_kv; bbase = bv_s2t; }
        }
        float w = W[k * stride + nc];
        g_wqkv[t][n * 256 + k] = __float2bfloat16(g[k] * w);

        red[k] = bln[k] * w;
        __syncthreads();
        for (int o = 128; o > 0; o >>= 1) {
            if (k < o) red[k] += red[k + o];
            __syncthreads();
        }
        if (k == 0) g_bfold[t][n] = red[0] + bbase[nc];
    } else {
        int nc = n - 512;
        const float* Wo = t ? Wo_t2s : Wo_s2t;
        g_wo[t][nc * 256 + k] = __float2bfloat16(Wo[k * 256 + nc]);
    }
}

// ---------------------------------------------------------------------------
// Kernel 2: fully fused block. grid (1024), block 512. One bc per block.
// ---------------------------------------------------------------------------
__global__ __launch_bounds__(512, 1) void fused_kernel(
    const float* __restrict__ x_spec, const float* __restrict__ x_spat,
    const float* __restrict__ bo_s2t, const float* __restrict__ bo_t2s,
    const float* __restrict__ gate_spec, const float* __restrict__ gate_spat,
    float* __restrict__ d_out)
{
    extern __shared__ __nv_bfloat16 sm[];
    int bc = blockIdx.x;
    int b = bc >> 7, c = bc & 127;
    int tid = threadIdx.x, wid = tid >> 5, lane = tid & 31;
    int gid = lane >> 2, tig = lane & 3;

    // ---- prefetch W(t=0) k16 chunk 0 into R2 buf0 (overlaps LN) ----
    {
        const __nv_bfloat16* Wg = g_wqkv[0];
        #pragma unroll
        for (int it = 0; it < 2; it++) {
            int idx = tid + it * 512;
            int n = idx >> 1, u = idx & 1;
            cp_async16(smaddr(sm + R2 + n * 24 + u * 8), Wg + n * 256 + u * 8);
        }
        cp_commit();
    }

    // ---- P0: LayerNorm cores (bf16) into SLOTA (spec) / SLOTB (spat) ----
    {
        int tw = wid >> 3;
        const float* x = tw ? x_spat : x_spec;
        __nv_bfloat16* core = sm + (tw ? SLOTB : SLOTA);
        #pragma unroll 2
        for (int rr = 0; rr < 8; rr++) {
            int r = (wid & 7) * 8 + rr;
            const float* src = x + (((size_t)b * 64 + r) * 128 + c) * 256 + lane * 8;
            float4 v0 = *(const float4*)src;
            float4 v1 = *(const float4*)(src + 4);
            float s1 = v0.x + v0.y + v0.z + v0.w + v1.x + v1.y + v1.z + v1.w;
            float s2 = v0.x*v0.x + v0.y*v0.y + v0.z*v0.z + v0.w*v0.w
                     + v1.x*v1.x + v1.y*v1.y + v1.z*v1.z + v1.w*v1.w;
            #pragma unroll
            for (int o = 16; o > 0; o >>= 1) {
                s1 += __shfl_xor_sync(0xffffffffu, s1, o);
                s2 += __shfl_xor_sync(0xffffffffu, s2, o);
            }
            float mu = s1 * (1.f / 256.f);
            float rinv = rsqrtf(s2 * (1.f / 256.f) - mu * mu + 1e-5f);
            uint4 pk;
            pk.x = pack_bf16((v0.x - mu) * rinv, (v0.y - mu) * rinv);
            pk.y = pack_bf16((v0.z - mu) * rinv, (v0.w - mu) * rinv);
            pk.z = pack_bf16((v1.x - mu) * rinv, (v1.y - mu) * rinv);
            pk.w = pack_bf16((v1.z - mu) * rinv, (v1.w - mu) * rinv);
            *(uint4*)(core + r * 264 + lane * 8) = pk;
        }
    }
    __syncthreads();

    // ---- P1/P2: QKV GEMMs. M=64, N=512, K=256 (16 k16 chunks, dbl-buffered)
    {
        int warp_m = wid >> 3, warp_n = wid & 7;   // 2 x 8 warps -> 32x64 tile
        uint32_t boff[4];
        #pragma unroll
        for (int tg = 0; tg < 4; tg++)
            boff[tg] = (((warp_n * 64 + tg * 16 + ((lane >> 4) << 3) + (lane & 7)) * 24 +
                         (((lane >> 3) & 1) << 3)) << 1);

        for (int t = 0; t < 2; t++) {
            const __nv_bfloat16* Wg = g_wqkv[t];
            uint32_t wb0 = (t == 0) ? (uint32_t)R2 : (uint32_t)SLOTA;
            uint32_t wb1 = (t == 0) ? (uint32_t)(R2 + 12288) : (uint32_t)WX;
            uint32_t aslot = (t == 0) ? (uint32_t)SLOTA : (uint32_t)SLOTB;
            __nv_bfloat16* outb = sm + ((t == 0) ? R1 : R2);

            uint32_t a_base[2];
            #pragma unroll
            for (int ti = 0; ti < 2; ti++)
                a_base[ti] = smaddr(sm + aslot) +
                    (((warp_m * 32 + ti * 16 + (lane & 15)) * 264 + ((lane >> 4) << 3)) << 1);

            float acc[2][8][4];
            #pragma unroll
            for (int ti = 0; ti < 2; ti++)
                #pragma unroll
                for (int tj = 0; tj < 8; tj++)
                    #pragma unroll
                    for (int q = 0; q < 4; q++) acc[ti][tj][q] = 0.f;

            #pragma unroll 4
            for (int cc = 0; cc < 16; cc++) {
                if (cc < 15) {
                    uint32_t dst = ((cc + 1) & 1) ? wb1 : wb0;
                    #pragma unroll
                    for (int it = 0; it < 2; it++) {
                        int idx = tid + it * 512;
                        int n = idx >> 1, u = idx & 1;
                        cp_async16(smaddr(sm + dst + n * 24 + u * 8),
                                   Wg + n * 256 + (cc + 1) * 16 + u * 8);
                    }
                    cp_commit();
                    cp_wait1();
                } else {
                    cp_wait0();
                }
                __syncthreads();

                uint32_t wbase = smaddr(sm + ((cc & 1) ? wb1 : wb0));
                uint32_t a[2][4], bfr[8][2];
                #pragma unroll
                for (int ti = 0; ti < 2; ti++)
                    ldsm4(a[ti][0], a[ti][1], a[ti][2], a[ti][3], a_base[ti] + (cc << 5));
                #pragma unroll
                for (int tg = 0; tg < 4; tg++)
                    ldsm4(bfr[2*tg][0], bfr[2*tg][1], bfr[2*tg+1][0], bfr[2*tg+1][1],
                          wbase + boff[tg]);
                #pragma unroll
                for (int ti = 0; ti < 2; ti++)
                    #pragma unroll
                    for (int tj = 0; tj < 8; tj++)
                        mma_bf16(acc[ti][tj], a[ti], bfr[tj]);
                __syncthreads();
            }

            if (t == 0) {
                // prefetch W(t=1) chunk 0 into SLOTA (core_spec now dead)
                const __nv_bfloat16* Wg1 = g_wqkv[1];
                #pragma unroll
                for (int it = 0; it < 2; it++) {
                    int idx = tid + it * 512;
                    int n = idx >> 1, u = idx & 1;
                    cp_async16(smaddr(sm + SLOTA + n * 24 + u * 8), Wg1 + n * 256 + u * 8);
                }
                cp_commit();
            }

            // epilogue: + bias, route to Q / K / Vt(subregions)
            const float* bfo = g_bfold[t];
            #pragma unroll
            for (int ti = 0; ti < 2; ti++) {
                int r0 = warp_m * 32 + ti * 16 + gid;
                #pragma unroll
                for (int tj = 0; tj < 8; tj++) {
                    int col = warp_n * 64 + tj * 8 + 2 * tig;
                    float b0 = bfo[col], b1 = bfo[col + 1];
                    float v00 = acc[ti][tj][0] + b0, v01 = acc[ti][tj][1] + b1;
                    float v10 = acc[ti][tj][2] + b0, v11 = acc[ti][tj][3] + b1;
                    if (col < 256) {
                        *(uint32_t*)(outb + QOFF + r0 * 264 + col)       = pack_bf16(v00, v01);
                        *(uint32_t*)(outb + QOFF + (r0 + 8) * 264 + col) = pack_bf16(v10, v11);
                    } else if (col < 384) {
                        int ck = col - 256;
                        *(uint32_t*)(outb + KOFF + r0 * 136 + ck)       = pack_bf16(v00, v01);
                        *(uint32_t*)(outb + KOFF + (r0 + 8) * 136 + ck) = pack_bf16(v10, v11);
                    } else {
                        int d = col - 384;
                        outb[VOFF + d * 72 + r0]           = __float2bfloat16(v00);
                        outb[VOFF + (d + 1) * 72 + r0]     = __float2bfloat16(v01);
                        outb[VOFF + d * 72 + r0 + 8]       = __float2bfloat16(v10);
                        outb[VOFF + (d + 1) * 72 + r0 + 8] = __float2bfloat16(v11);
                    }
                }
            }
            __syncthreads();
        }
    }

    // ---- P3: attention. 2 passes x 16 warp-tasks. softmax in registers ----
    {
        int kvh = (wid >> 2) & 3, hh = (wid >> 1) & 1, mh = wid & 1;
        const float scale = 0.17677669529663687f;  // 1/sqrt(32)

        #pragma unroll
        for (int pass = 0; pass < 2; pass++) {
            int t = pass;
            uint32_t qreg = t ? (uint32_t)R2 : (uint32_t)R1;
            uint32_t kvreg = t ? (uint32_t)R1 : (uint32_t)R2;
            int colb = (kvh * 2 + hh) * 32;

            // QK^T: 32 rows x 64 keys, K=32
            uint32_t qaddr[2], kaddr[4];
            #pragma unroll
            for (int ti = 0; ti < 2; ti++)
                qaddr[ti] = smaddr(sm + qreg + QOFF) +
                    (((mh * 32 + ti * 16 + (lane & 15)) * 264 + colb + ((lane >> 4) << 3)) << 1);
            #pragma unroll
            for (int tg = 0; tg < 4; tg++)
                kaddr[tg] = smaddr(sm + kvreg + KOFF) +
                    (((tg * 16 + ((lane >> 4) << 3) + (lane & 7)) * 136 + kvh * 32 +
                      (((lane >> 3) & 1) << 3)) << 1);

            float acc[2][8][4];
            #pragma unroll
            for (int ti = 0; ti < 2; ti++)
                #pragma unroll
                for (int tj = 0; tj < 8; tj++)
                    #pragma unroll
                    for (int q = 0; q < 4; q++) acc[ti][tj][q] = 0.f;

            #pragma unroll
            for (int ksi = 0; ksi < 2; ksi++) {
                uint32_t a[2][4], bfr[8][2];
                #pragma unroll
                for (int ti = 0; ti < 2; ti++)
                    ldsm4(a[ti][0], a[ti][1], a[ti][2], a[ti][3], qaddr[ti] + (ksi << 5));
                #pragma unroll
                for (int tg = 0; tg < 4; tg++)
                    ldsm4(bfr[2*tg][0], bfr[2*tg][1], bfr[2*tg+1][0], bfr[2*tg+1][1],
                          kaddr[tg] + (ksi << 5));
                #pragma unroll
                for (int ti = 0; ti < 2; ti++)
                    #pragma unroll
                    for (int tj = 0; tj < 8; tj++)
                        mma_bf16(acc[ti][tj], a[ti], bfr[tj]);
            }

            // softmax in registers (row stats across 4-lane groups)
            #pragma unroll
            for (int ti = 0; ti < 2; ti++) {
                float m0 = -3.0e38f, m1 = -3.0e38f;
                #pragma unroll
                for (int tj = 0; tj < 8; tj++) {
                    #pragma unroll
                    for (int q = 0; q < 4; q++) acc[ti][tj][q] *= scale;
                    m0 = fmaxf(m0, fmaxf(acc[ti][tj][0], acc[ti][tj][1]));
                    m1 = fmaxf(m1, fmaxf(acc[ti][tj][2], acc[ti][tj][3]));
                }
                m0 = fmaxf(m0, __shfl_xor_sync(0xffffffffu, m0, 1));
                m0 = fmaxf(m0, __shfl_xor_sync(0xffffffffu, m0, 2));
                m1 = fmaxf(m1, __shfl_xor_sync(0xffffffffu, m1, 1));
                m1 = fmaxf(m1, __shfl_xor_sync(0xffffffffu, m1, 2));
                float s0 = 0.f, s1 = 0.f;
                #pragma unroll
                for (int tj = 0; tj < 8; tj++) {
                    acc[ti][tj][0] = __expf(acc[ti][tj][0] - m0);
                    acc[ti][tj][1] = __expf(acc[ti][tj][1] - m0);
                    acc[ti][tj][2] = __expf(acc[ti][tj][2] - m1);
                    acc[ti][tj][3] = __expf(acc[ti][tj][3] - m1);
                    s0 += acc[ti][tj][0] + acc[ti][tj][1];
                    s1 += acc[ti][tj][2] + acc[ti][tj][3];
                }
                s0 += __shfl_xor_sync(0xffffffffu, s0, 1);
                s0 += __shfl_xor_sync(0xffffffffu, s0, 2);
                s1 += __shfl_xor_sync(0xffffffffu, s1, 1);
                s1 += __shfl_xor_sync(0xffffffffu, s1, 2);
                float r0 = 1.f / s0, r1 = 1.f / s1;
                #pragma unroll
                for (int tj = 0; tj < 8; tj++) {
                    acc[ti][tj][0] *= r0; acc[ti][tj][1] *= r0;
                    acc[ti][tj][2] *= r1; acc[ti][tj][3] *= r1;
                }
            }

            // PV: K=64, N=32
            uint32_t vaddr[2];
            #pragma unroll
            for (int tg = 0; tg < 2; tg++)
                vaddr[tg] = smaddr(sm + kvreg + VOFF) +
                    (((kvh * 32 + tg * 16 + ((lane >> 4) << 3) + (lane & 7)) * 72 +
                      (((lane >> 3) & 1) << 3)) << 1);

            float o[2][4][4];
            #pragma unroll
            for (int ti = 0; ti < 2; ti++)
                #pragma unroll
                for (int tj = 0; tj < 4; tj++)
                    #pragma unroll
                    for (int q = 0; q < 4; q++) o[ti][tj][q] = 0.f;

            #pragma unroll
            for (int ksi = 0; ksi < 4; ksi++) {
                uint32_t bv[4][2];
                ldsm4(bv[0][0], bv[0][1], bv[1][0], bv[1][1], vaddr[0] + (ksi << 5));
                ldsm4(bv[2][0], bv[2][1], bv[3][0], bv[3][1], vaddr[1] + (ksi << 5));
                #pragma unroll
                for (int ti = 0; ti < 2; ti++) {
                    int tj = ksi * 2;
                    uint32_t ap[4];
                    ap[0] = pack_bf16(acc[ti][tj][0], acc[ti][tj][1]);
                    ap[1] = pack_bf16(acc[ti][tj][2], acc[ti][tj][3]);
                    ap[2] = pack_bf16(acc[ti][tj+1][0], acc[ti][tj+1][1]);
                    ap[3] = pack_bf16(acc[ti][tj+1][2], acc[ti][tj+1][3]);
                    #pragma unroll
                    for (int tj2 = 0; tj2 < 4; tj2++)
                        mma_bf16(o[ti][tj2], ap, bv[tj2]);
                }
            }

            // att -> slot (bf16)
            __nv_bfloat16* att = sm + (t ? SLOTB : SLOTA);
            #pragma unroll
            for (int ti = 0; ti < 2; ti++) {
                int r0 = mh * 32 + ti * 16 + gid;
                #pragma unroll
                for (int tj2 = 0; tj2 < 4; tj2++) {
                    int col = colb + tj2 * 8 + 2 * tig;
                    *(uint32_t*)(att + r0 * 264 + col)       = pack_bf16(o[ti][tj2][0], o[ti][tj2][1]);
                    *(uint32_t*)(att + (r0 + 8) * 264 + col) = pack_bf16(o[ti][tj2][2], o[ti][tj2][3]);
                }
            }
        }
    }
    __syncthreads();

    // ---- P4: O-proj + bias + gate + residual. warps 0-7: spec, 8-15: spat ----
    {
        int t = wid >> 3;
        int w8 = wid & 7, warp_m = w8 >> 2, warp_n = w8 & 3;   // 2 x 4 -> 32x64 tile
        const __nv_bfloat16* Wo = g_wo[t];
        const float* bo = t ? bo_t2s : bo_s2t;
        const float* xr = t ? x_spat : x_spec;
        float gv = t ? gate_spat[0] : gate_spec[0];
        float gate = 1.f / (1.f + __expf(-gv));
        uint32_t aslot = t ? (uint32_t)SLOTB : (uint32_t)SLOTA;
        int tid256 = tid & 255;
        uint32_t wbuf0 = (uint32_t)R1 + (t * 2 + 0) * 10240;
        uint32_t wbuf1 = (uint32_t)R1 + (t * 2 + 1) * 10240;

        // prefetch Wo chunk 0 (k32)
        #pragma unroll
        for (int it = 0; it < 4; it++) {
            int idx = tid256 + it * 256;
            int n = idx >> 2, u = idx & 3;
            cp_async16(smaddr(sm + wbuf0 + n * 40 + u * 8), Wo + n * 256 + u * 8);
        }
        cp_commit();

        uint32_t a_base[2];
        #pragma unroll
        for (int ti = 0; ti < 2; ti++)
            a_base[ti] = smaddr(sm + aslot) +
                (((warp_m * 32 + ti * 16 + (lane & 15)) * 264 + ((lane >> 4) << 3)) << 1);
        uint32_t boff[4];
        #pragma unroll
        for (int tg = 0; tg < 4; tg++)
            boff[tg] = (((warp_n * 64 + tg * 16 + ((lane >> 4) << 3) + (lane & 7)) * 40 +
                         (((lane >> 3) & 1) << 3)) << 1);

        float acc[2][8][4];
        #pragma unroll
        for (int ti = 0; ti < 2; ti++)
            #pragma unroll
            for (int tj = 0; tj < 8; tj++)
                #pragma unroll
                for (int q = 0; q < 4; q++) acc[ti][tj][q] = 0.f;

        #pragma unroll 2
        for (int cc = 0; cc < 8; cc++) {
            if (cc < 7) {
                uint32_t dst = ((cc + 1) & 1) ? wbuf1 : wbuf0;
                #pragma unroll
                for (int it = 0; it < 4; it++) {
                    int idx = tid256 + it * 256;
                    int n = idx >> 2, u = idx & 3;
                    cp_async16(smaddr(sm + dst + n * 40 + u * 8),
                               Wo + n * 256 + (cc + 1) * 32 + u * 8);
                }
                cp_commit();
                cp_wait1();
            } else {
                cp_wait0();
            }
            __syncthreads();

            uint32_t wbase = smaddr(sm + ((cc & 1) ? wbuf1 : wbuf0));
            #pragma unroll
            for (int ksi = 0; ksi < 2; ksi++) {
                uint32_t a[2][4], bfr[8][2];
                #pragma unroll
                for (int ti = 0; ti < 2; ti++)
                    ldsm4(a[ti][0], a[ti][1], a[ti][2], a[ti][3],
                          a_base[ti] + (cc << 6) + (ksi << 5));
                #pragma unroll
                for (int tg = 0; tg < 4; tg++)
                    ldsm4(bfr[2*tg][0], bfr[2*tg][1], bfr[2*tg+1][0], bfr[2*tg+1][1],
                          wbase + boff[tg] + (ksi << 5));
                #pragma unroll
                for (int ti = 0; ti < 2; ti++)
                    #pragma unroll
                    for (int tj = 0; tj < 8; tj++)
                        mma_bf16(acc[ti][tj], a[ti], bfr[tj]);
            }
            __syncthreads();
        }

        // epilogue: bias + gate + residual -> d_out
        #pragma unroll
        for (int ti = 0; ti < 2; ti++) {
            #pragma unroll
            for (int half = 0; half < 2; half++) {
                int s = warp_m * 32 + ti * 16 + gid + half * 8;
                size_t gb = (((size_t)b * 64 + s) * 128 + c) * 256;
                #pragma unroll
                for (int tj = 0; tj < 8; tj++) {
                    int col = warp_n * 64 + tj * 8 + 2 * tig;
                    float a0 = acc[ti][tj][half * 2 + 0] + bo[col];
                    float a1 = acc[ti][tj][half * 2 + 1] + bo[col + 1];
                    float2 xv = *(const float2*)(xr + gb + col);
                    float2 ov = make_float2(xv.x + gate * a0, xv.y + gate * a1);
                    *(float2*)(d_out + (size_t)t * BSCD + gb + col) = ov;
                }
            }
        }
    }
}

// ---------------------------------------------------------------------------
// Host launcher
// ---------------------------------------------------------------------------
extern "C" void kernel_launch(void* const* d_in, const int* in_sizes, int n_in,
                              void* d_out, int out_size)
{
    const float* x_spec      = (const float*)d_in[0];
    const float* x_spat      = (const float*)d_in[1];
    const float* ln_spec_q_g = (const float*)d_in[2];
    const float* ln_spec_q_b = (const float*)d_in[3];
    const float* ln_spec_kv_g= (const float*)d_in[4];
    const float* ln_spec_kv_b= (const float*)d_in[5];
    const float* ln_spat_q_g = (const float*)d_in[6];
    const float* ln_spat_q_b = (const float*)d_in[7];
    const float* ln_spat_kv_g= (const float*)d_in[8];
    const float* ln_spat_kv_b= (const float*)d_in[9];
    const float* Wq_s2t = (const float*)d_in[10];
    const float* bq_s2t = (const float*)d_in[11];
    const float* Wk_s2t = (const float*)d_in[12];
    const float* bk_s2t = (const float*)d_in[13];
    const float* Wv_s2t = (const float*)d_in[14];
    const float* bv_s2t = (const float*)d_in[15];
    const float* Wo_s2t = (const float*)d_in[16];
    const float* bo_s2t = (const float*)d_in[17];
    const float* Wq_t2s = (const float*)d_in[18];
    const float* bq_t2s = (const float*)d_in[19];
    const float* Wk_t2s = (const float*)d_in[20];
    const float* bk_t2s = (const float*)d_in[21];
    const float* Wv_t2s = (const float*)d_in[22];
    const float* bv_t2s = (const float*)d_in[23];
    const float* Wo_t2s = (const float*)d_in[24];
    const float* bo_t2s = (const float*)d_in[25];
    const float* gate_spec = (const float*)d_in[26];
    const float* gate_spat = (const float*)d_in[27];
    float* out = (float*)d_out;

    cudaFuncSetAttribute(fused_kernel, cudaFuncAttributeMaxDynamicSharedMemorySize, SMEM_BYTES);

    prep_kernel<<<dim3(768, 2), 256>>>(
        Wq_s2t, bq_s2t, Wk_s2t, bk_s2t, Wv_s2t, bv_s2t,
        Wq_t2s, bq_t2s, Wk_t2s, bk_t2s, Wv_t2s, bv_t2s,
        Wo_s2t, Wo_t2s,
        ln_spec_q_g, ln_spec_q_b, ln_spec_kv_g, ln_spec_kv_b,
        ln_spat_q_g, ln_spat_q_b, ln_spat_kv_g, ln_spat_kv_b);

    fused_kernel<<<1024, 512, SMEM_BYTES>>>(
        x_spec, x_spat, bo_s2t, bo_t2s, gate_spec, gate_spat, out);
}